// round 16
// baseline (speedup 1.0000x reference)
#include <cuda_runtime.h>
#include <cuda_fp16.h>
#include <cstdint>

// Problem constants (fixed by the dataset)
#define NN   4096
#define FDIM 256
#define BB   8
#define MTOT (BB * NN)          // 32768 rows
#define WPR  (NN / 32)
#define MAXD 128

// -------- scratch (static __device__ arrays; no allocation allowed) --------
// g_adj / g_deg are zero-initialized at module load; k_agg's tail re-zeroes
// them each call, so every kernel_launch invocation starts from zero state.
__device__ unsigned g_adj[NN * WPR];
__device__ int      g_deg[NN];
__device__ int      g_nbr[NN * MAXD];
__device__ __align__(16) __half g_xth[(size_t)MTOT * FDIM];  // 16 MB fp16 xt

// ---------------------------------------------------------------------------
// Kernel 1: FUSED edge-build + GEMM.
//   edges: one edge per thread (256 CTAs x 512 thr == E); atomicOr issued
//          first, chain finished after B preload -> latency hidden.
//   gemm : xt = x @ W. CTA tile M=128 x N=256 (FULL N): x is read exactly
//          once chip-wide (A L2 traffic halved vs N=128 tiles).
//          512 threads, 16 warps in 4(wm) x 4(wn); per-warp mainloop is the
//          round-10 proven 32x64 tile (acc[2][8][4], ldsm.x4.trans).
// ---------------------------------------------------------------------------
#define BSTR2 264                  // B smem row stride in halves (256 + 8 pad)
#define S_TOT (256 * BSTR2 * 2)    // 135168 bytes

extern __shared__ char dsm[];

__device__ __forceinline__ uint32_t smem_u32(const void* p) {
    uint32_t a;
    asm("{ .reg .u64 t; cvta.to.shared.u64 t, %1; cvt.u32.u64 %0, t; }"
        : "=r"(a) : "l"(p));
    return a;
}
__device__ __forceinline__ void ldsm_x4_t(uint32_t* r, uint32_t addr) {
    asm volatile("ldmatrix.sync.aligned.m8n8.x4.trans.shared.b16 {%0,%1,%2,%3}, [%4];"
                 : "=r"(r[0]), "=r"(r[1]), "=r"(r[2]), "=r"(r[3]) : "r"(addr));
}
__device__ __forceinline__ void mma_f16(float* c, const uint32_t* a,
                                        const uint32_t* b) {
    asm volatile(
        "mma.sync.aligned.m16n8k16.row.col.f32.f16.f16.f32 "
        "{%0,%1,%2,%3}, {%4,%5,%6,%7}, {%8,%9}, {%0,%1,%2,%3};"
        : "+f"(c[0]), "+f"(c[1]), "+f"(c[2]), "+f"(c[3])
        : "r"(a[0]), "r"(a[1]), "r"(a[2]), "r"(a[3]), "r"(b[0]), "r"(b[1]));
}

__global__ void __launch_bounds__(512)
k_gemm_tc(const float* __restrict__ x, const float* __restrict__ w,
          const int* __restrict__ ei, int E) {
    const int tid  = threadIdx.x;
    const int lane = tid & 31;
    const int wrp  = tid >> 5;        // 0..15
    const int wm   = wrp & 3;         // 0..3 (32-row block)
    const int wn   = wrp >> 2;        // 0..3 (64-col block)
    const int m0   = blockIdx.x * 128;
    const uint32_t sb = smem_u32(dsm);

    // ---- edge work, part 1: issue the dedup atomicOr ----
    const int gid = (blockIdx.x << 9) + tid;
    int esrc = -1, edst = 0;
    unsigned eold = 0, emask = 0;
    if (gid < E) {
        esrc  = ei[gid];
        edst  = ei[E + gid];
        emask = 1u << (edst & 31);
        eold  = atomicOr(&g_adj[esrc * WPR + (edst >> 5)], emask);
    }

    // ---- B preload: w [256 k][256 n] fp32 -> smem [k][n] fp16 (coalesced) ----
    #pragma unroll
    for (int q = 0; q < 32; q++) {
        int i  = q * 512 + tid;       // float4 index, 0..16383
        int k  = i >> 6;              // 64 float4 per 256-wide row
        int c4 = i & 63;
        float4 f = *(const float4*)(w + (size_t)k * FDIM + c4 * 4);
        __half2 h0 = __float22half2_rn(make_float2(f.x, f.y));
        __half2 h1 = __float22half2_rn(make_float2(f.z, f.w));
        *(uint2*)(dsm + k * (BSTR2 * 2) + c4 * 8) =
            make_uint2(*(uint32_t*)&h0, *(uint32_t*)&h1);
    }

    // ---- edge work, part 2: finish the dedup chain (latency overlapped) ----
    if (esrc >= 0 && !(eold & emask)) {
        int pos = atomicAdd(&g_deg[esrc], 1);
        if (pos < MAXD) g_nbr[esrc * MAXD + pos] = edst;
    }
    // safety net if E ever exceeds total threads
    for (int e2 = gid + (gridDim.x << 9); e2 < E; e2 += (gridDim.x << 9)) {
        int s = ei[e2], d = ei[E + e2];
        unsigned mk = 1u << (d & 31);
        unsigned od = atomicOr(&g_adj[s * WPR + (d >> 5)], mk);
        if (!(od & mk)) {
            int pos = atomicAdd(&g_deg[s], 1);
            if (pos < MAXD) g_nbr[s * MAXD + pos] = d;
        }
    }
    __syncthreads();

    // ---- mainloop (round-10 proven per-warp structure; B via ldsm.trans) ----
    const float* ap = x + (size_t)(m0 + wm * 32 + (lane >> 2)) * FDIM +
                      ((lane & 3) << 1);
    // trans tiles: lanes0-7: klo/n+0, 8-15: khi/n+0, 16-23: klo/n+8, 24-31: khi/n+8
    const uint32_t bbase = sb +
        (uint32_t)(((lane >> 3) & 1) * 8 + (lane & 7)) * (BSTR2 * 2) +
        (uint32_t)(wn * 64 + ((lane >> 4) & 1) * 8) * 2;

    float acc[2][8][4];
    #pragma unroll
    for (int i = 0; i < 2; i++)
        #pragma unroll
        for (int j = 0; j < 8; j++)
            #pragma unroll
            for (int r = 0; r < 4; r++) acc[i][j][r] = 0.f;

    float2 pv[2][4];
    #pragma unroll
    for (int i = 0; i < 2; i++) {
        const float* p = ap + i * 16 * FDIM;
        pv[i][0] = *(const float2*)(p);
        pv[i][1] = *(const float2*)(p + 8 * FDIM);
        pv[i][2] = *(const float2*)(p + 8);
        pv[i][3] = *(const float2*)(p + 8 * FDIM + 8);
    }

    #pragma unroll
    for (int kk = 0; kk < 16; kk++) {
        float2 nv[2][4];
        if (kk + 1 < 16) {
            const int kn = (kk + 1) * 16;
            #pragma unroll
            for (int i = 0; i < 2; i++) {
                const float* p = ap + i * 16 * FDIM + kn;
                nv[i][0] = *(const float2*)(p);
                nv[i][1] = *(const float2*)(p + 8 * FDIM);
                nv[i][2] = *(const float2*)(p + 8);
                nv[i][3] = *(const float2*)(p + 8 * FDIM + 8);
            }
        }

        uint32_t aF[2][4];
        #pragma unroll
        for (int i = 0; i < 2; i++)
            #pragma unroll
            for (int q = 0; q < 4; q++) {
                __half2 h = __float22half2_rn(pv[i][q]);
                aF[i][q] = *(uint32_t*)&h;
            }

        const uint32_t krow = (uint32_t)(kk * 16) * (BSTR2 * 2);
        #pragma unroll
        for (int j2 = 0; j2 < 4; j2++) {
            uint32_t bb[4];
            ldsm_x4_t(bb, bbase + krow + (uint32_t)(j2 * 16) * 2);
            #pragma unroll
            for (int i = 0; i < 2; i++) {
                mma_f16(acc[i][2 * j2 + 0], aF[i], &bb[0]);
                mma_f16(acc[i][2 * j2 + 1], aF[i], &bb[2]);
            }
        }

        #pragma unroll
        for (int i = 0; i < 2; i++)
            #pragma unroll
            for (int q = 0; q < 4; q++) pv[i][q] = nv[i][q];
    }

    #pragma unroll
    for (int i = 0; i < 2; i++) {
        #pragma unroll
        for (int j = 0; j < 8; j++) {
            int m = m0 + wm * 32 + i * 16 + (lane >> 2);
            int n = wn * 64 + j * 8 + (lane & 3) * 2;
            *(__half2*)&g_xth[(size_t)m * FDIM + n] =
                __float22half2_rn(make_float2(acc[i][j][0], acc[i][j][1]));
            *(__half2*)&g_xth[(size_t)(m + 8) * FDIM + n] =
                __float22half2_rn(make_float2(acc[i][j][2], acc[i][j][3]));
        }
    }
}

// ---------------------------------------------------------------------------
// Kernel 2: sparse aggregation (round-10 proven 4-way loop) + rezero tail.
// ---------------------------------------------------------------------------
__global__ void __launch_bounds__(256)
k_agg(const float* __restrict__ bias, float* __restrict__ out) {
    const int src  = blockIdx.x;
    const int tid  = threadIdx.x;
    const int b    = tid >> 5;           // batch = warp
    const int lane = tid & 31;
    const int f    = lane << 3;          // 8 features per lane

    __shared__ int snb[MAXD];
    int deg = g_deg[src];
    if (deg > MAXD) deg = MAXD;
    if (tid < deg) snb[tid] = g_nbr[src * MAXD + tid];
    __syncthreads();

    // rezero for the next call (each block owns its src's slots)
    if (tid < WPR) g_adj[src * WPR + tid] = 0u;
    if (tid == 0)  g_deg[src] = 0;

    const __half* __restrict__ base = g_xth + (size_t)b * NN * FDIM + f;

    float acc[8];
    #pragma unroll
    for (int q = 0; q < 8; q++) acc[q] = 0.f;

    int i = 0;
    for (; i + 4 <= deg; i += 4) {
        uint4 u0 = *(const uint4*)(base + ((size_t)snb[i]     << 8));
        uint4 u1 = *(const uint4*)(base + ((size_t)snb[i + 1] << 8));
        uint4 u2 = *(const uint4*)(base + ((size_t)snb[i + 2] << 8));
        uint4 u3 = *(const uint4*)(base + ((size_t)snb[i + 3] << 8));
        #pragma unroll
        for (int q = 0; q < 4; q++) {
            __half2 s01 = __hadd2(((const __half2*)&u0)[q],
                                  ((const __half2*)&u1)[q]);
            __half2 s23 = __hadd2(((const __half2*)&u2)[q],
                                  ((const __half2*)&u3)[q]);
            float2 f01 = __half22float2(s01);
            float2 f23 = __half22float2(s23);
            acc[2 * q]     += f01.x + f23.x;
            acc[2 * q + 1] += f01.y + f23.y;
        }
    }
    for (; i < deg; i++) {
        uint4 u0 = *(const uint4*)(base + ((size_t)snb[i] << 8));
        #pragma unroll
        for (int q = 0; q < 4; q++) {
            float2 fv = __half22float2(((const __half2*)&u0)[q]);
            acc[2 * q]     += fv.x;
            acc[2 * q + 1] += fv.y;
        }
    }

    const float inv = 1.0f / ((float)deg + 1e-6f);
    const float4 bf0 = *(const float4*)&bias[f];
    const float4 bf1 = *(const float4*)&bias[f + 4];

    float* dst = &out[((size_t)b * NN + src) * FDIM + f];
    *(float4*)(dst)     = make_float4(acc[0] * inv + bf0.x, acc[1] * inv + bf0.y,
                                      acc[2] * inv + bf0.z, acc[3] * inv + bf0.w);
    *(float4*)(dst + 4) = make_float4(acc[4] * inv + bf1.x, acc[5] * inv + bf1.y,
                                      acc[6] * inv + bf1.z, acc[7] * inv + bf1.w);
}

// ---------------------------------------------------------------------------
extern "C" void kernel_launch(void* const* d_in, const int* in_sizes, int n_in,
                              void* d_out, int out_size) {
    const float* x    = (const float*)d_in[0];   // (8, 4096, 256) f32
    const int*   ei   = (const int*)  d_in[1];   // (2, 131072) i32
    const float* w    = (const float*)d_in[2];   // (256, 256) f32
    const float* bias = (const float*)d_in[3];   // (256,) f32
    float* out = (float*)d_out;

    const int E = in_sizes[1] / 2;

    cudaFuncSetAttribute(k_gemm_tc, cudaFuncAttributeMaxDynamicSharedMemorySize,
                         S_TOT);

    k_gemm_tc<<<MTOT / 128, 512, S_TOT>>>(x, w, ei, E);
    k_agg<<<NN, 256>>>(bias, out);
}